// round 15
// baseline (speedup 1.0000x reference)
#include <cuda_runtime.h>
#include <cuda_bf16.h>
#include <math.h>

// Problem constants
#define TQ  1024
#define BQ  64
#define IQ  256
#define HQ  512
#define H4Q 2048
#define OQ  128
#define MQ  65536  // B*T

// lstm smem layout (floats)
#define WS_FLOATS (HQ * 64)       // resident W slice: [k 0..511][c 0..63] = 32768
#define HS_PITCH  36
#define HS_FLOATS (HQ * HS_PITCH) // h: [k 0..511][b_local 0..31], pitch 36 = 18432
#define GS_PITCH  68              // 68 = 4*17: every row 16B-aligned
#define GS_FLOATS (32 * GS_PITCH) // 2176 (one partial gate stash)
#define SMEM_FLOATS (WS_FLOATS + HS_FLOATS + 2 * GS_FLOATS)
#define SMEM_BYTES  (SMEM_FLOATS * 4)   // 222,208 B (<= 227 KB cap)

// ---------------------------------------------------------------------------
// Scratch (static __device__ arrays: allocation-free per harness rules)
// ---------------------------------------------------------------------------
__device__ __align__(256) float g_xg[(size_t)2 * MQ * H4Q];          // [dir][b*T+t][4H] (1 GiB)
__device__ __align__(256) float g_y [(size_t)MQ * 2 * HQ];           // [b][t][dir*H+j]  (256 MB)
__device__ __align__(256) float g_hn[2 * 2 * HQ * BQ];               // [parity][dir][j][b]
__device__ __align__(256) float g_c [2 * BQ * HQ];                   // [dir][b][j]
__device__ __align__(256) float g_wstage[(size_t)2 * 32 * HQ * 64];  // [dir][jt][k][c] (16 MB)
__device__ unsigned g_bar_count[4];
__device__ unsigned g_bar_epoch[4];

__device__ __forceinline__ float sigmf(float x) { return 1.0f / (1.0f + __expf(-x)); }

#define NAMED_BAR(id, cnt) \
    asm volatile("bar.sync %0, %1;" :: "r"(id), "r"(cnt) : "memory")

// ---------------------------------------------------------------------------
// Init: zero state + barriers, gather W_hh into per-CTA contiguous stage:
//   g_wstage[dir][jt][k][c] = W_hh_dir[(c>>4)*H + jt*16 + (c&15)][k]
// Runs every launch (graph replays must be deterministic).
// ---------------------------------------------------------------------------
__global__ void init_kernel(const float* __restrict__ Whh_f,
                            const float* __restrict__ Whh_b) {
    int idx = blockIdx.x * blockDim.x + threadIdx.x;

    const int WS_TOTAL = 2 * 32 * HQ * 64;  // 4,194,304
    if (idx < WS_TOTAL) {
        int dir = idx >> 20;
        int rem = idx & ((1 << 20) - 1);
        int jt  = rem >> 15;
        int r2  = rem & 32767;
        int k   = r2 >> 6;
        int c   = r2 & 63;
        int gr  = (c >> 4) * HQ + jt * 16 + (c & 15);
        const float* W = dir ? Whh_b : Whh_f;
        g_wstage[idx] = W[(size_t)gr * HQ + k];
    }
    if (idx < 2 * 2 * HQ * BQ) g_hn[idx] = 0.0f;
    if (idx < 2 * BQ * HQ)     g_c[idx]  = 0.0f;
    if (idx < 4) { g_bar_count[idx] = 0u; g_bar_epoch[idx] = 0u; }
}

// ---------------------------------------------------------------------------
// C[M][N] = A[M][K] * W[N][K]^T + bias1[N] (+ bias2[N])
// 128x128 tile, 256 threads, 8x8 microtile, k-chunk 16, register prefetch.
// (Round-6 proven version: plain scalar FFMA. Already FMA-bound: 1 B/FMA.)
// ---------------------------------------------------------------------------
__global__ __launch_bounds__(256, 2) void gemm_abt_kernel(
    const float* __restrict__ A, const float* __restrict__ W,
    const float* __restrict__ bias1, const float* __restrict__ bias2,
    float* __restrict__ C, int M, int N, int K)
{
    __shared__ float As[16][132];
    __shared__ float Bs[16][132];

    const int tid = threadIdx.x;
    const int tx  = tid & 15;
    const int ty  = tid >> 4;
    const int n0  = blockIdx.x * 128;
    const int m0  = blockIdx.y * 128;

    const int lr = tid >> 1;
    const int lc = (tid & 1) << 3;

    const float* Arow = A + (size_t)(m0 + lr) * K + lc;
    const float* Wrow = W + (size_t)(n0 + lr) * K + lc;

    float acc[8][8];
#pragma unroll
    for (int i = 0; i < 8; i++)
#pragma unroll
        for (int j = 0; j < 8; j++) acc[i][j] = 0.0f;

    float4 pa0 = *(const float4*)(Arow);
    float4 pa1 = *(const float4*)(Arow + 4);
    float4 pb0 = *(const float4*)(Wrow);
    float4 pb1 = *(const float4*)(Wrow + 4);

    for (int k0 = 0; k0 < K; k0 += 16) {
        As[lc+0][lr]=pa0.x; As[lc+1][lr]=pa0.y; As[lc+2][lr]=pa0.z; As[lc+3][lr]=pa0.w;
        As[lc+4][lr]=pa1.x; As[lc+5][lr]=pa1.y; As[lc+6][lr]=pa1.z; As[lc+7][lr]=pa1.w;
        Bs[lc+0][lr]=pb0.x; Bs[lc+1][lr]=pb0.y; Bs[lc+2][lr]=pb0.z; Bs[lc+3][lr]=pb0.w;
        Bs[lc+4][lr]=pb1.x; Bs[lc+5][lr]=pb1.y; Bs[lc+6][lr]=pb1.z; Bs[lc+7][lr]=pb1.w;
        __syncthreads();

        if (k0 + 16 < K) {
            pa0 = *(const float4*)(Arow + k0 + 16);
            pa1 = *(const float4*)(Arow + k0 + 20);
            pb0 = *(const float4*)(Wrow + k0 + 16);
            pb1 = *(const float4*)(Wrow + k0 + 20);
        }

#pragma unroll
        for (int kk = 0; kk < 16; kk++) {
            float4 x0 = *(const float4*)&As[kk][ty * 8];
            float4 x1 = *(const float4*)&As[kk][ty * 8 + 4];
            float4 y0 = *(const float4*)&Bs[kk][tx * 8];
            float4 y1 = *(const float4*)&Bs[kk][tx * 8 + 4];
            float av[8] = {x0.x, x0.y, x0.z, x0.w, x1.x, x1.y, x1.z, x1.w};
            float bv[8] = {y0.x, y0.y, y0.z, y0.w, y1.x, y1.y, y1.z, y1.w};
#pragma unroll
            for (int i = 0; i < 8; i++)
#pragma unroll
                for (int j = 0; j < 8; j++)
                    acc[i][j] = fmaf(av[i], bv[j], acc[i][j]);
        }
        __syncthreads();
    }

    float bv[8];
#pragma unroll
    for (int j = 0; j < 8; j++) {
        int n = n0 + tx * 8 + j;
        float b = bias1 ? bias1[n] : 0.0f;
        if (bias2) b += bias2[n];
        bv[j] = b;
    }
#pragma unroll
    for (int i = 0; i < 8; i++) {
        float* crow = C + (size_t)(m0 + ty * 8 + i) * N + n0 + tx * 8;
#pragma unroll
        for (int j = 0; j < 8; j++) crow[j] = acc[i][j] + bv[j];
    }
}

// ---------------------------------------------------------------------------
// Persistent LSTM: ONE kernel, all 1024 steps, both directions.
// 128 CTAs (jt 0..31, bt 0..1, dir 0..1), all co-resident (1 CTA/SM).
// CTA tile: 32 b x 64 gate-cols; 256 threads = 4 k-quarters x 64 threads,
// thread tile 4b x 8c (1.5 B/FMA, r13 proven).
// r14: sync-overhead squeeze.
//  - Each quarter stages ITS OWN 128-k h chunk, then passes a 2-warp named
//    barrier (id 1+q) straight into its GEMM — no full-CTA stage sync.
//  - Merge pairing (q0->A,q2+=A) and (q1->B,q3+=B) uses two 128-thread named
//    barriers (ids 5,6) instead of a full __syncthreads.
// W resident in smem; c in regs; parity double-buffer; 4 group barriers.
// ---------------------------------------------------------------------------
__global__ __launch_bounds__(256, 1) void lstm_persistent_kernel()
{
    extern __shared__ float sm[];
    float* ws  = sm;                           // [k][c],       512 x 64
    float* hs  = sm + WS_FLOATS;               // [k][b_local], 512 x 36 pitch
    float* gSA = sm + WS_FLOATS + HS_FLOATS;   // partial gates (q0 + q2)
    float* gSB = gSA + GS_FLOATS;              // partial gates (q1 + q3)

    const int jt  = blockIdx.x;
    const int bt  = blockIdx.y;
    const int dir = blockIdx.z;
    const int grp = dir * 2 + bt;
    const int j0  = jt * 16;
    const int b0  = bt * 32;

    const int tid  = threadIdx.x;
    const int q    = tid >> 6;            // k-quarter 0..3
    const int qt   = tid & 63;            // thread within quarter
    const int ty   = qt >> 3;             // 0..7 -> b rows r0 = ty*4 .. +3
    const int tx   = qt & 7;              // 0..7 -> cols  c0 = tx*8 .. +7
    const int r0   = ty * 4;
    const int c0   = tx * 8;
    const int kb   = q * 128;             // this quarter's k base
    const int gr   = (c0 >> 4) * HQ + j0 + (c0 & 15);  // cols c0..c0+7 contiguous in-gate

    // stage resident W slice (once per kernel)
    const float* wsrc = g_wstage + ((size_t)dir * 32 + jt) * WS_FLOATS;
    for (int i = tid * 4; i < WS_FLOATS; i += 1024)
        *(float4*)&ws[i] = *(const float4*)&wsrc[i];

    // c-state in registers: thread owns u = tid*2 + {0,1} -> (bl,jl)
    float creg[2] = {0.0f, 0.0f};

    const float* xgd = g_xg + (size_t)dir * MQ * H4Q;

    __syncthreads();  // ws ready

    // xg prefetch for step 0: only quarter 0 seeds from xg (4 rows x 8 cols)
    float4 xp[4][2];
#pragma unroll
    for (int i = 0; i < 4; i++) {
        xp[i][0] = make_float4(0.f, 0.f, 0.f, 0.f);
        xp[i][1] = make_float4(0.f, 0.f, 0.f, 0.f);
    }
    int t0 = dir ? (TQ - 1) : 0;
    if (q == 0) {
#pragma unroll
        for (int i = 0; i < 4; i++) {
            const float* xr = xgd + ((size_t)(b0 + r0 + i) * TQ + t0) * H4Q + gr;
            xp[i][0] = *(const float4*)(xr);
            xp[i][1] = *(const float4*)(xr + 4);
        }
    }

    for (int s = 0; s < TQ; s++) {
        const int t = dir ? (TQ - 1 - s) : s;
        const float* hread  = g_hn + (size_t)((s & 1) * 2 + dir) * (HQ * BQ);
        float*       hwrite = g_hn + (size_t)(((s + 1) & 1) * 2 + dir) * (HQ * BQ);

        // init accumulators (quarter 0 carries xg+biases, others 0)
        float acc[4][8];
#pragma unroll
        for (int i = 0; i < 4; i++) {
            acc[i][0] = xp[i][0].x; acc[i][1] = xp[i][0].y;
            acc[i][2] = xp[i][0].z; acc[i][3] = xp[i][0].w;
            acc[i][4] = xp[i][1].x; acc[i][5] = xp[i][1].y;
            acc[i][6] = xp[i][1].z; acc[i][7] = xp[i][1].w;
        }

        if (q == 0 && s + 1 < TQ) {  // prefetch next step's xg (read-only)
            int tn = dir ? (t - 1) : (t + 1);
#pragma unroll
            for (int i = 0; i < 4; i++) {
                const float* xr = xgd + ((size_t)(b0 + r0 + i) * TQ + tn) * H4Q + gr;
                xp[i][0] = *(const float4*)(xr);
                xp[i][1] = *(const float4*)(xr + 4);
            }
        }

        // stage THIS quarter's h chunk: 128 k-rows x 32 b = 1024 float4,
        // 16 per thread (coalesced LDG.128), then 2-warp named barrier.
#pragma unroll
        for (int n = 0; n < 16; n++) {
            int f   = qt + n * 64;          // 0..1023
            int k   = kb + (f >> 3);        // this quarter's rows
            int off = (f & 7) << 2;
            *(float4*)&hs[k * HS_PITCH + off] =
                *(const float4*)(hread + (size_t)k * BQ + b0 + off);
        }
        NAMED_BAR(1 + q, 64);

        // GEMM partial over this quarter's 128 k values.
        // Per k: 2x LDS.128 (w, 32B) + 1x LDS.128 (h, 16B) -> 32 FFMA.
        const float* wq = ws + kb * 64 + c0;
        const float* hq = hs + kb * HS_PITCH + r0;
        float4 w0 = *(const float4*)(wq);
        float4 w1 = *(const float4*)(wq + 4);
        float4 hv = *(const float4*)(hq);
#pragma unroll 4
        for (int k = 0; k < 127; k++) {
            float4 w0n = *(const float4*)(wq + (k + 1) * 64);
            float4 w1n = *(const float4*)(wq + (k + 1) * 64 + 4);
            float4 hn  = *(const float4*)(hq + (k + 1) * HS_PITCH);
            float av[4] = {hv.x, hv.y, hv.z, hv.w};
            float wv[8] = {w0.x, w0.y, w0.z, w0.w, w1.x, w1.y, w1.z, w1.w};
#pragma unroll
            for (int i = 0; i < 4; i++)
#pragma unroll
                for (int j = 0; j < 8; j++)
                    acc[i][j] = fmaf(av[i], wv[j], acc[i][j]);
            w0 = w0n; w1 = w1n; hv = hn;
        }
        {
            float av[4] = {hv.x, hv.y, hv.z, hv.w};
            float wv[8] = {w0.x, w0.y, w0.z, w0.w, w1.x, w1.y, w1.z, w1.w};
#pragma unroll
            for (int i = 0; i < 4; i++)
#pragma unroll
                for (int j = 0; j < 8; j++)
                    acc[i][j] = fmaf(av[i], wv[j], acc[i][j]);
        }

        // partial merge: q0->A, q1->B; pairing barriers; q2+=A, q3+=B
        float* gH = (q & 1) ? gSB : gSA;
        if (q < 2) {
#pragma unroll
            for (int i = 0; i < 4; i++) {
                *(float4*)&gH[(r0 + i) * GS_PITCH + c0] =
                    make_float4(acc[i][0], acc[i][1], acc[i][2], acc[i][3]);
                *(float4*)&gH[(r0 + i) * GS_PITCH + c0 + 4] =
                    make_float4(acc[i][4], acc[i][5], acc[i][6], acc[i][7]);
            }
        }
        NAMED_BAR(5 + (q & 1), 128);   // (q0,q2) on id5, (q1,q3) on id6
        if (q >= 2) {
#pragma unroll
            for (int i = 0; i < 4; i++) {
                float4 v0 = *(const float4*)&gH[(r0 + i) * GS_PITCH + c0];
                float4 v1 = *(const float4*)&gH[(r0 + i) * GS_PITCH + c0 + 4];
                v0.x += acc[i][0]; v0.y += acc[i][1]; v0.z += acc[i][2]; v0.w += acc[i][3];
                v1.x += acc[i][4]; v1.y += acc[i][5]; v1.z += acc[i][6]; v1.w += acc[i][7];
                *(float4*)&gH[(r0 + i) * GS_PITCH + c0]     = v0;
                *(float4*)&gH[(r0 + i) * GS_PITCH + c0 + 4] = v1;
            }
        }
        __syncthreads();   // A and B complete; update reads both

        // LSTM update: 512 (b,j) pairs, 2 per thread. Gate order i,f,g,o.
#pragma unroll
        for (int u2 = 0; u2 < 2; u2++) {
            int u  = tid * 2 + u2;
            int bl = u >> 4;
            int jl = u & 15;
            float ig = sigmf(gSA[bl * GS_PITCH + jl]      + gSB[bl * GS_PITCH + jl]);
            float fg = sigmf(gSA[bl * GS_PITCH + 16 + jl] + gSB[bl * GS_PITCH + 16 + jl]);
            float gg = tanhf(gSA[bl * GS_PITCH + 32 + jl] + gSB[bl * GS_PITCH + 32 + jl]);
            float og = sigmf(gSA[bl * GS_PITCH + 48 + jl] + gSB[bl * GS_PITCH + 48 + jl]);
            float cn = fmaf(fg, creg[u2], ig * gg);
            float hn = og * tanhf(cn);
            creg[u2] = cn;
            int b = b0 + bl;
            int j = j0 + jl;
            hwrite[(size_t)j * BQ + b] = hn;
            g_y[(size_t)(b * TQ + t) * (2 * HQ) + (size_t)dir * HQ + j] = hn;
        }

        // group barrier (skip after last step; kernel exit synchronizes)
        if (s + 1 < TQ) {
            __syncthreads();   // also protects gSA/gSB + hs reuse next step
            if (tid == 0) {
                __threadfence();
                unsigned prev = atomicAdd(&g_bar_count[grp], 1u);
                if (prev == 31u) {
                    g_bar_count[grp] = 0u;
                    __threadfence();
                    atomicExch(&g_bar_epoch[grp], (unsigned)(s + 1));
                } else {
                    while (atomicAdd(&g_bar_epoch[grp], 0u) < (unsigned)(s + 1))
                        __nanosleep(20);
                    __threadfence();
                }
            }
            __syncthreads();
        }
    }

    // final c-state to global for the tail copy
#pragma unroll
    for (int u2 = 0; u2 < 2; u2++) {
        int u  = tid * 2 + u2;
        int bl = u >> 4;
        int jl = u & 15;
        g_c[(size_t)dir * BQ * HQ + (size_t)(b0 + bl) * HQ + (j0 + jl)] = creg[u2];
    }
}

// ---------------------------------------------------------------------------
// Final h/c into d_out tail. Final h is parity 0 ((1023+1)&1 == 0), [j][b].
// ---------------------------------------------------------------------------
__global__ void final_copy_kernel(float* __restrict__ hn_out, float* __restrict__ cn_out) {
    int i = blockIdx.x * blockDim.x + threadIdx.x;
    if (i < 2 * BQ * HQ) {
        int dir = i / (BQ * HQ);
        int rem = i - dir * (BQ * HQ);
        int b = rem / HQ;
        int j = rem - b * HQ;
        hn_out[i] = g_hn[(size_t)dir * (HQ * BQ) + (size_t)j * BQ + b];
        cn_out[i] = g_c[i];
    }
}

// ---------------------------------------------------------------------------
extern "C" void kernel_launch(void* const* d_in, const int* in_sizes, int n_in,
                              void* d_out, int out_size) {
    const float* inputs = (const float*)d_in[0];
    const float* W_ih_f = (const float*)d_in[1];
    const float* W_hh_f = (const float*)d_in[2];
    const float* b_ih_f = (const float*)d_in[3];
    const float* b_hh_f = (const float*)d_in[4];
    const float* W_ih_b = (const float*)d_in[5];
    const float* W_hh_b = (const float*)d_in[6];
    const float* b_ih_b = (const float*)d_in[7];
    const float* b_hh_b = (const float*)d_in[8];
    const float* W_out  = (const float*)d_in[9];
    const float* b_out  = (const float*)d_in[10];
    float* out = (float*)d_out;

    float *p_xg = nullptr, *p_y = nullptr;
    cudaGetSymbolAddress((void**)&p_xg, g_xg);
    cudaGetSymbolAddress((void**)&p_y,  g_y);

    // opt in to 217 KB dynamic smem for the persistent kernel
    cudaFuncSetAttribute(lstm_persistent_kernel,
                         cudaFuncAttributeMaxDynamicSharedMemorySize, SMEM_BYTES);

    // Node 1: init (state zero + W gather + barrier reset)
    init_kernel<<<(2 * 32 * HQ * 64 + 255) / 256, 256>>>(W_hh_f, W_hh_b);

    // Nodes 2-3: xg[dir] = inputs * W_ih^T + (b_ih + b_hh)
    dim3 g1(H4Q / 128, MQ / 128);  // (16, 512)
    gemm_abt_kernel<<<g1, 256>>>(inputs, W_ih_f, b_ih_f, b_hh_f,
                                 p_xg, MQ, H4Q, IQ);
    gemm_abt_kernel<<<g1, 256>>>(inputs, W_ih_b, b_ih_b, b_hh_b,
                                 p_xg + (size_t)MQ * H4Q, MQ, H4Q, IQ);

    // Node 4: all 1024 recurrence steps in one persistent kernel
    dim3 gs(32, 2, 2);  // 128 CTAs, all co-resident
    lstm_persistent_kernel<<<gs, 256, SMEM_BYTES>>>();

    // Node 5: out = y * W_out^T + b_out
    dim3 g3(OQ / 128, MQ / 128);  // (1, 512)
    gemm_abt_kernel<<<g3, 256>>>(p_y, W_out, b_out, nullptr,
                                 out, MQ, OQ, 2 * HQ);

    // Node 6: h_n / c_n tail (only if the output buffer includes them)
    long long need = (long long)MQ * OQ + 4LL * BQ * HQ;
    if ((long long)out_size >= need)
        final_copy_kernel<<<(2 * BQ * HQ + 255) / 256, 256>>>(
            out + (size_t)MQ * OQ,
            out + (size_t)MQ * OQ + 2 * BQ * HQ);
}

// round 17
// speedup vs baseline: 1.6603x; 1.6603x over previous
#include <cuda_runtime.h>
#include <cuda_bf16.h>
#include <math.h>
#include <stdint.h>

#define TQ  1024
#define BQ  64
#define IQ  256
#define HQ  512
#define H4Q 2048
#define OQ  128
#define MQ  65536

// lstm smem layout (bytes). W resident [c][k] bf16 swizzled, hi+lo.
// h per-step [b][k] bf16 swizzled, hi+lo. Gate stash fp32 [32][68].
#define SM_W_HI 0          // 64 KB
#define SM_W_LO 65536      // 64 KB
#define SM_H_HI 131072     // 32 KB
#define SM_H_LO 163840     // 32 KB
#define SM_GS   196608     // 32*68*4 = 8704 B
#define SMEM_TOTAL (196608 + 32 * 68 * 4)   // 205,312 B (< 227 KB cap)

// ---------------------------------------------------------------------------
// Scratch (static __device__ arrays: allocation-free per harness rules)
// ---------------------------------------------------------------------------
__device__ __align__(256) float g_xg[(size_t)2 * MQ * H4Q];     // [dir][b*T+t][4H]
__device__ __align__(256) float g_y [(size_t)MQ * 2 * HQ];      // [b][t][dir*H+j]
__device__ __align__(256) unsigned short g_hbf_hi[2 * 2 * BQ * HQ]; // [par][dir][b][k]
__device__ __align__(256) unsigned short g_hbf_lo[2 * 2 * BQ * HQ];
__device__ __align__(256) float g_c [2 * BQ * HQ];              // [dir][b][j]
// pre-swizzled W_hh bf16 images: per (dir,jt): [hi 32768 ushorts][lo 32768]
__device__ __align__(256) unsigned short g_wimg[(size_t)2 * 32 * 65536];
__device__ unsigned g_bar_count[4];
__device__ unsigned g_bar_epoch[4];

__device__ __forceinline__ float sigmf(float x) { return 1.0f / (1.0f + __expf(-x)); }

__device__ __forceinline__ uint32_t smem_u32(const void* p) {
    uint32_t a;
    asm("{ .reg .u64 t; cvta.to.shared.u64 t, %1; cvt.u32.u64 %0, t; }" : "=r"(a) : "l"(p));
    return a;
}
#define LDSM_X4(r0, r1, r2, r3, a) \
    asm volatile("ldmatrix.sync.aligned.m8n8.x4.shared.b16 {%0,%1,%2,%3}, [%4];" \
        : "=r"(r0), "=r"(r1), "=r"(r2), "=r"(r3) : "r"(a) : "memory")
#define LDSM_X2(r0, r1, a) \
    asm volatile("ldmatrix.sync.aligned.m8n8.x2.shared.b16 {%0,%1}, [%2];" \
        : "=r"(r0), "=r"(r1) : "r"(a) : "memory")
#define MMA_BF16(d, a0, a1, a2, a3, b0, b1) \
    asm volatile("mma.sync.aligned.m16n8k16.row.col.f32.bf16.bf16.f32 " \
        "{%0,%1,%2,%3}, {%4,%5,%6,%7}, {%8,%9}, {%0,%1,%2,%3};" \
        : "+f"((d)[0]), "+f"((d)[1]), "+f"((d)[2]), "+f"((d)[3]) \
        : "r"(a0), "r"(a1), "r"(a2), "r"(a3), "r"(b0), "r"(b1))

// ---------------------------------------------------------------------------
// Init: zero states + barriers; build swizzled bf16 hi/lo W images.
// W row c of CTA (dir,jt) = W_hh[(c>>4)*H + jt*16 + (c&15)][k].
// ushort index within image: part*32768 + c*512 + (k ^ ((c&7)<<3)).
// ---------------------------------------------------------------------------
__global__ void init_kernel(const float* __restrict__ Whh_f,
                            const float* __restrict__ Whh_b) {
    int idx = blockIdx.x * blockDim.x + threadIdx.x;
    const int W_TOTAL = 2 * 32 * 2 * 64 * 512;  // 4,194,304
    if (idx < W_TOTAL) {
        int k    = idx & 511;
        int c    = (idx >> 9) & 63;
        int part = (idx >> 15) & 1;
        int jt   = (idx >> 16) & 31;
        int dir  = idx >> 21;
        int gr   = (c >> 4) * HQ + jt * 16 + (c & 15);
        const float* W = dir ? Whh_b : Whh_f;
        float w = W[(size_t)gr * HQ + k];
        __nv_bfloat16 hi = __float2bfloat16(w);
        __nv_bfloat16 v  = part ? __float2bfloat16(w - __bfloat162float(hi)) : hi;
        g_wimg[((size_t)(dir * 32 + jt)) * 65536 + part * 32768
               + c * 512 + (k ^ ((c & 7) << 3))] = *reinterpret_cast<unsigned short*>(&v);
    }
    if (idx < 2 * 2 * BQ * HQ) { g_hbf_hi[idx] = 0; g_hbf_lo[idx] = 0; }
    if (idx < 2 * BQ * HQ)     g_c[idx] = 0.0f;
    if (idx < 4) { g_bar_count[idx] = 0u; g_bar_epoch[idx] = 0u; }
}

// ---------------------------------------------------------------------------
// SIMT SGEMM for phases 1 & 3 (round-6 proven)
// ---------------------------------------------------------------------------
__global__ __launch_bounds__(256, 2) void gemm_abt_kernel(
    const float* __restrict__ A, const float* __restrict__ W,
    const float* __restrict__ bias1, const float* __restrict__ bias2,
    float* __restrict__ C, int M, int N, int K)
{
    __shared__ float As[16][132];
    __shared__ float Bs[16][132];
    const int tid = threadIdx.x;
    const int tx  = tid & 15, ty = tid >> 4;
    const int n0  = blockIdx.x * 128, m0 = blockIdx.y * 128;
    const int lr  = tid >> 1, lc = (tid & 1) << 3;
    const float* Arow = A + (size_t)(m0 + lr) * K + lc;
    const float* Wrow = W + (size_t)(n0 + lr) * K + lc;

    float acc[8][8];
#pragma unroll
    for (int i = 0; i < 8; i++)
#pragma unroll
        for (int j = 0; j < 8; j++) acc[i][j] = 0.0f;

    float4 pa0 = *(const float4*)(Arow);
    float4 pa1 = *(const float4*)(Arow + 4);
    float4 pb0 = *(const float4*)(Wrow);
    float4 pb1 = *(const float4*)(Wrow + 4);

    for (int k0 = 0; k0 < K; k0 += 16) {
        As[lc+0][lr]=pa0.x; As[lc+1][lr]=pa0.y; As[lc+2][lr]=pa0.z; As[lc+3][lr]=pa0.w;
        As[lc+4][lr]=pa1.x; As[lc+5][lr]=pa1.y; As[lc+6][lr]=pa1.z; As[lc+7][lr]=pa1.w;
        Bs[lc+0][lr]=pb0.x; Bs[lc+1][lr]=pb0.y; Bs[lc+2][lr]=pb0.z; Bs[lc+3][lr]=pb0.w;
        Bs[lc+4][lr]=pb1.x; Bs[lc+5][lr]=pb1.y; Bs[lc+6][lr]=pb1.z; Bs[lc+7][lr]=pb1.w;
        __syncthreads();
        if (k0 + 16 < K) {
            pa0 = *(const float4*)(Arow + k0 + 16);
            pa1 = *(const float4*)(Arow + k0 + 20);
            pb0 = *(const float4*)(Wrow + k0 + 16);
            pb1 = *(const float4*)(Wrow + k0 + 20);
        }
#pragma unroll
        for (int kk = 0; kk < 16; kk++) {
            float4 x0 = *(const float4*)&As[kk][ty * 8];
            float4 x1 = *(const float4*)&As[kk][ty * 8 + 4];
            float4 y0 = *(const float4*)&Bs[kk][tx * 8];
            float4 y1 = *(const float4*)&Bs[kk][tx * 8 + 4];
            float av[8] = {x0.x, x0.y, x0.z, x0.w, x1.x, x1.y, x1.z, x1.w};
            float bv[8] = {y0.x, y0.y, y0.z, y0.w, y1.x, y1.y, y1.z, y1.w};
#pragma unroll
            for (int i = 0; i < 8; i++)
#pragma unroll
                for (int j = 0; j < 8; j++)
                    acc[i][j] = fmaf(av[i], bv[j], acc[i][j]);
        }
        __syncthreads();
    }
    float bv[8];
#pragma unroll
    for (int j = 0; j < 8; j++) {
        int n = n0 + tx * 8 + j;
        float b = bias1 ? bias1[n] : 0.0f;
        if (bias2) b += bias2[n];
        bv[j] = b;
    }
#pragma unroll
    for (int i = 0; i < 8; i++) {
        float* crow = C + (size_t)(m0 + ty * 8 + i) * N + n0 + tx * 8;
#pragma unroll
        for (int j = 0; j < 8; j++) crow[j] = acc[i][j] + bv[j];
    }
}

// ---------------------------------------------------------------------------
// Persistent LSTM via warp-level bf16x3 mma.sync (sm_80-class PTX; compiles
// for plain sm_103 -- tcgen05 does NOT, per r16 ptxas evidence).
// 128 CTAs (jt 0..31, bt 0..1, dir 0..1), 1 CTA/SM.
// CTA tile 32b x 64c, K=512. 8 warps = wy(2 m-tiles of 16) x wx(4 gates);
// each warp: two 16x8 D tiles, 32 k-steps of m16n8k16, 3 mma/tile/kstep
// (Ah.Bh, Ah.Bl, Al.Bh) with split hh/cross accumulators.
// W (hi+lo, 128 KB) resident in smem; h (hi+lo, 64 KB) staged per step;
// c in regs; parity double-buffer; 4 group epoch barriers.
// ---------------------------------------------------------------------------
__global__ __launch_bounds__(256, 1) void lstm_mma_kernel()
{
    extern __shared__ char smem[];
    float* gS = (float*)(smem + SM_GS);
    const uint32_t sb = smem_u32(smem);

    const int jt  = blockIdx.x;
    const int bt  = blockIdx.y;
    const int dir = blockIdx.z;
    const int grp = dir * 2 + bt;
    const int j0  = jt * 16;
    const int b0  = bt * 32;

    const int tid  = threadIdx.x;
    const int wid  = tid >> 5, lane = tid & 31;
    const int wx   = wid & 3;          // gate 0..3
    const int wy   = wid >> 2;         // m-tile 0..1

    // stage resident W image (128 KB) once
    {
        const uint4* src = (const uint4*)(g_wimg + (size_t)(dir * 32 + jt) * 65536);
#pragma unroll
        for (int n = 0; n < 32; n++) {
            int i = tid + n * 256;
            *(uint4*)(smem + (size_t)i * 16) = src[i];
        }
    }

    // ldmatrix lane-constant address components
    const int rowA = wy * 16 + (lane & 7) + (lane & 8);   // A matrix row (local b)
    const uint32_t kA16 = ((lane >> 4) & 1) * 16;          // A k-byte offset within step
    const uint32_t swA  = (uint32_t)(lane & 7) << 4;
    const uint32_t kB16 = ((lane >> 3) & 1) * 16;          // B k-byte offset
    const uint32_t swB  = (uint32_t)(lane & 7) << 4;
    const uint32_t aHi  = sb + SM_H_HI + (uint32_t)rowA * 1024;
    const uint32_t aLo  = sb + SM_H_LO + (uint32_t)rowA * 1024;
    const uint32_t bHi0 = sb + SM_W_HI + (uint32_t)(wx * 16 + (lane & 7)) * 1024;
    const uint32_t bHi1 = bHi0 + 8 * 1024;
    const uint32_t bLo0 = bHi0 + (SM_W_LO - SM_W_HI);
    const uint32_t bLo1 = bHi1 + (SM_W_LO - SM_W_HI);

    float creg[2] = {0.0f, 0.0f};
    const float* xgd = g_xg + (size_t)dir * MQ * H4Q;

    __syncthreads();  // W resident

    for (int s = 0; s < TQ; s++) {
        const int t   = dir ? (TQ - 1 - s) : s;
        const int par = s & 1;
        const unsigned short* hhi = g_hbf_hi + (size_t)(par * 2 + dir) * (BQ * HQ);
        const unsigned short* hlo = g_hbf_lo + (size_t)(par * 2 + dir) * (BQ * HQ);

        // stage h hi+lo (64 KB): 4096 uint4, 16 per thread, swizzled
#pragma unroll
        for (int n = 0; n < 16; n++) {
            int f    = tid + n * 256;
            int part = f >> 11;
            int rem  = f & 2047;
            int b    = rem >> 6;
            int kc   = rem & 63;
            const uint4* src = (const uint4*)(part ? hlo : hhi) + ((size_t)(b0 + b) * 64 + kc);
            uint32_t dst = (part ? SM_H_LO : SM_H_HI) + (uint32_t)b * 1024
                         + (((uint32_t)kc * 16) ^ (((uint32_t)b & 7) << 4));
            *(uint4*)(smem + dst) = *src;
        }

        // xg for this warp's D tiles: [tile][rowhalf] float2
        float2 xv[2][2];
        {
            int r0g = b0 + wy * 16 + (lane >> 2);
#pragma unroll
            for (int nt = 0; nt < 2; nt++) {
                int cl = nt * 8 + (lane & 3) * 2;                 // c&15
                int gr = wx * HQ + j0 + cl;
                xv[nt][0] = *(const float2*)(xgd + ((size_t)r0g * TQ + t) * H4Q + gr);
                xv[nt][1] = *(const float2*)(xgd + ((size_t)(r0g + 8) * TQ + t) * H4Q + gr);
            }
        }
        __syncthreads();

        // mma mainloop: 32 k-steps of 16
        float dhh[2][4] = {{0, 0, 0, 0}, {0, 0, 0, 0}};
        float dcx[2][4] = {{0, 0, 0, 0}, {0, 0, 0, 0}};
#pragma unroll 4
        for (int ks = 0; ks < 32; ks++) {
            uint32_t offA = (((uint32_t)ks * 32 + kA16) ^ swA);
            uint32_t offB = (((uint32_t)ks * 32 + kB16) ^ swB);
            uint32_t ah0, ah1, ah2, ah3, al0, al1, al2, al3;
            uint32_t bh00, bh01, bh10, bh11, bl00, bl01, bl10, bl11;
            LDSM_X4(ah0, ah1, ah2, ah3, aHi + offA);
            LDSM_X4(al0, al1, al2, al3, aLo + offA);
            LDSM_X2(bh00, bh01, bHi0 + offB);
            LDSM_X2(bh10, bh11, bHi1 + offB);
            LDSM_X2(bl00, bl01, bLo0 + offB);
            LDSM_X2(bl10, bl11, bLo1 + offB);
            MMA_BF16(dhh[0], ah0, ah1, ah2, ah3, bh00, bh01);
            MMA_BF16(dhh[1], ah0, ah1, ah2, ah3, bh10, bh11);
            MMA_BF16(dcx[0], ah0, ah1, ah2, ah3, bl00, bl01);
            MMA_BF16(dcx[1], ah0, ah1, ah2, ah3, bl10, bl11);
            MMA_BF16(dcx[0], al0, al1, al2, al3, bh00, bh01);
            MMA_BF16(dcx[1], al0, al1, al2, al3, bh10, bh11);
        }

        // D + xg -> gate stash
        {
            int r0l = wy * 16 + (lane >> 2);
#pragma unroll
            for (int nt = 0; nt < 2; nt++) {
                int c = wx * 16 + nt * 8 + (lane & 3) * 2;
                *(float2*)&gS[r0l * 68 + c] = make_float2(
                    dhh[nt][0] + dcx[nt][0] + xv[nt][0].x,
                    dhh[nt][1] + dcx[nt][1] + xv[nt][0].y);
                *(float2*)&gS[(r0l + 8) * 68 + c] = make_float2(
                    dhh[nt][2] + dcx[nt][2] + xv[nt][1].x,
                    dhh[nt][3] + dcx[nt][3] + xv[nt][1].y);
            }
        }
        __syncthreads();

        // LSTM update: 512 (b,j) pairs, 2 per thread. Gate order i,f,g,o.
        unsigned short* whi = g_hbf_hi + (size_t)((par ^ 1) * 2 + dir) * (BQ * HQ);
        unsigned short* wlo = g_hbf_lo + (size_t)((par ^ 1) * 2 + dir) * (BQ * HQ);
#pragma unroll
        for (int u2 = 0; u2 < 2; u2++) {
            int u  = tid * 2 + u2;
            int bl = u >> 4;
            int jl = u & 15;
            float ig = sigmf(gS[bl * 68 + jl]);
            float fg = sigmf(gS[bl * 68 + 16 + jl]);
            float gg = tanhf(gS[bl * 68 + 32 + jl]);
            float og = sigmf(gS[bl * 68 + 48 + jl]);
            float cn = fmaf(fg, creg[u2], ig * gg);
            float hn = og * tanhf(cn);
            creg[u2] = cn;
            int b = b0 + bl;
            int j = j0 + jl;
            __nv_bfloat16 hi = __float2bfloat16(hn);
            __nv_bfloat16 lo = __float2bfloat16(hn - __bfloat162float(hi));
            whi[(size_t)b * HQ + j] = *reinterpret_cast<unsigned short*>(&hi);
            wlo[(size_t)b * HQ + j] = *reinterpret_cast<unsigned short*>(&lo);
            g_y[(size_t)(b * TQ + t) * (2 * HQ) + (size_t)dir * HQ + j] = hn;
        }

        // group epoch barrier (skip after last step)
        if (s + 1 < TQ) {
            __syncthreads();
            if (tid == 0) {
                __threadfence();
                unsigned prev = atomicAdd(&g_bar_count[grp], 1u);
                if (prev == 31u) {
                    g_bar_count[grp] = 0u;
                    __threadfence();
                    atomicExch(&g_bar_epoch[grp], (unsigned)(s + 1));
                } else {
                    while (atomicAdd(&g_bar_epoch[grp], 0u) < (unsigned)(s + 1))
                        __nanosleep(20);
                    __threadfence();
                }
            }
            __syncthreads();
        }
    }

    // final c-state for tail copy
#pragma unroll
    for (int u2 = 0; u2 < 2; u2++) {
        int u  = tid * 2 + u2;
        int bl = u >> 4;
        int jl = u & 15;
        g_c[(size_t)dir * BQ * HQ + (size_t)(b0 + bl) * HQ + (j0 + jl)] = creg[u2];
    }
}

// ---------------------------------------------------------------------------
// Final h/c tail. Final h lives in parity 0 ((1023+1)&1 == 0), [dir][b][j].
// ---------------------------------------------------------------------------
__global__ void final_copy_kernel(float* __restrict__ hn_out, float* __restrict__ cn_out) {
    int i = blockIdx.x * blockDim.x + threadIdx.x;
    if (i < 2 * BQ * HQ) {
        unsigned short uh = g_hbf_hi[i], ul = g_hbf_lo[i];  // parity 0 block
        hn_out[i] = __bfloat162float(*reinterpret_cast<__nv_bfloat16*>(&uh))
                  + __bfloat162float(*reinterpret_cast<__nv_bfloat16*>(&ul));
        cn_out[i] = g_c[i];
    }
}

// ---------------------------------------------------------------------------
extern "C" void kernel_launch(void* const* d_in, const int* in_sizes, int n_in,
                              void* d_out, int out_size) {
    const float* inputs = (const float*)d_in[0];
    const float* W_ih_f = (const float*)d_in[1];
    const float* W_hh_f = (const float*)d_in[2];
    const float* b_ih_f = (const float*)d_in[3];
    const float* b_hh_f = (const float*)d_in[4];
    const float* W_ih_b = (const float*)d_in[5];
    const float* W_hh_b = (const float*)d_in[6];
    const float* b_ih_b = (const float*)d_in[7];
    const float* b_hh_b = (const float*)d_in[8];
    const float* W_out  = (const float*)d_in[9];
    const float* b_out  = (const float*)d_in[10];
    float* out = (float*)d_out;

    float *p_xg = nullptr, *p_y = nullptr;
    cudaGetSymbolAddress((void**)&p_xg, g_xg);
    cudaGetSymbolAddress((void**)&p_y,  g_y);

    cudaFuncSetAttribute(lstm_mma_kernel,
                         cudaFuncAttributeMaxDynamicSharedMemorySize, SMEM_TOTAL);

    // Node 1: init (state zero + swizzled bf16 W images + barrier reset)
    init_kernel<<<(2 * 32 * 2 * 64 * 512 + 255) / 256, 256>>>(W_hh_f, W_hh_b);

    // Nodes 2-3: xg[dir] = inputs * W_ih^T + (b_ih + b_hh)
    dim3 g1(H4Q / 128, MQ / 128);
    gemm_abt_kernel<<<g1, 256>>>(inputs, W_ih_f, b_ih_f, b_hh_f,
                                 p_xg, MQ, H4Q, IQ);
    gemm_abt_kernel<<<g1, 256>>>(inputs, W_ih_b, b_ih_b, b_hh_b,
                                 p_xg + (size_t)MQ * H4Q, MQ, H4Q, IQ);

    // Node 4: all 1024 steps, mma.sync persistent kernel
    dim3 gs(32, 2, 2);
    lstm_mma_kernel<<<gs, 256, SMEM_TOTAL>>>();

    // Node 5: out = y * W_out^T + b_out
    dim3 g3(OQ / 128, MQ / 128);
    gemm_abt_kernel<<<g3, 256>>>(p_y, W_out, b_out, nullptr,
                                 out, MQ, OQ, 2 * HQ);

    // Node 6: h_n / c_n tail
    long long need = (long long)MQ * OQ + 4LL * BQ * HQ;
    if ((long long)out_size >= need)
        final_copy_kernel<<<(2 * BQ * HQ + 255) / 256, 256>>>(
            out + (size_t)MQ * OQ,
            out + (size_t)MQ * OQ + 2 * BQ * HQ);
}